// round 1
// baseline (speedup 1.0000x reference)
#include <cuda_runtime.h>
#include <cuda_bf16.h>
#include <math.h>

#define B_  16
#define C_  256
#define T_  2048
#define CQK_ 32

// Scratch (allocation-free rule: __device__ globals)
__device__ float g_Q[B_ * CQK_ * T_];   // [B][32][T]
__device__ float g_K[B_ * CQK_ * T_];   // [B][32][T]
__device__ float g_V[B_ * C_  * T_];    // [B][256][T]

// ---------------------------------------------------------------------------
// Projection: y[b,o,t] = sum_c W[o,c] * x[b,c,t] + bias[o]
// Block tile: 32 (o) x 128 (t), K-chunks of 32. 256 threads, each 4x4 outputs.
// grid: (T/128, O/32, B)
// ---------------------------------------------------------------------------
__global__ void __launch_bounds__(256) proj_kernel(
    const float* __restrict__ x, const float* __restrict__ W,
    const float* __restrict__ bias, float* __restrict__ y, int O)
{
    __shared__ float Ws[32 * 33];    // [o][c] stride 33
    __shared__ float xs[32 * 132];   // [c][t] stride 132 (128 + pad)

    const int t0 = blockIdx.x * 128;
    const int o0 = blockIdx.y * 32;
    const int b  = blockIdx.z;
    const int tid = threadIdx.x;
    const int oi = tid >> 5;          // 0..7
    const int ti = tid & 31;          // 0..31

    float acc[4][4];
#pragma unroll
    for (int a = 0; a < 4; a++)
#pragma unroll
        for (int bb = 0; bb < 4; bb++) acc[a][bb] = 0.f;

    for (int k0 = 0; k0 < C_; k0 += 32) {
        // load W tile 32x32
#pragma unroll
        for (int k = 0; k < 4; k++) {
            int idx = tid + 256 * k;
            int o = idx >> 5, c = idx & 31;
            Ws[o * 33 + c] = W[(o0 + o) * C_ + k0 + c];
        }
        // load x tile 32x128 as float4
#pragma unroll
        for (int k = 0; k < 4; k++) {
            int f = tid + 256 * k;
            int c = f >> 5, t4 = f & 31;
            const float4 v = *(const float4*)&x[((size_t)b * C_ + (k0 + c)) * T_ + t0 + t4 * 4];
            *(float4*)&xs[c * 132 + t4 * 4] = v;
        }
        __syncthreads();

#pragma unroll 8
        for (int c = 0; c < 32; c++) {
            float w[4], xv[4];
#pragma unroll
            for (int a = 0; a < 4; a++) w[a] = Ws[(oi * 4 + a) * 33 + c];
#pragma unroll
            for (int bb = 0; bb < 4; bb++) xv[bb] = xs[c * 132 + ti + 32 * bb];
#pragma unroll
            for (int a = 0; a < 4; a++)
#pragma unroll
                for (int bb = 0; bb < 4; bb++) acc[a][bb] += w[a] * xv[bb];
        }
        __syncthreads();
    }

#pragma unroll
    for (int a = 0; a < 4; a++) {
        const int o = o0 + oi * 4 + a;
        const float bo = bias[o];
#pragma unroll
        for (int bb = 0; bb < 4; bb++) {
            const int t = t0 + ti + 32 * bb;
            y[((size_t)b * O + o) * T_ + t] = acc[a][bb] + bo;
        }
    }
}

// ---------------------------------------------------------------------------
// Fused attention: per block = (batch, 64-wide t tile). Online softmax over
// 64 s-tiles of 32. Thread (tr, cc): rows t = t0+tr*4+i (i<4), cols c = cc+16j.
// ---------------------------------------------------------------------------
#define TT 64
#define TS 32
// smem float offsets
#define QS_OFF 0              // 32 x 68
#define KS_OFF (32*68)        // 32 x 36
#define PS_OFF (KS_OFF+32*36) // 64 x 33
#define VS_OFF (PS_OFF+64*33) // 32 x 257  ([s][c])
#define SMEM_FLOATS (VS_OFF + 32*257)

__global__ void __launch_bounds__(256) attn_kernel(
    const float* __restrict__ x, float* __restrict__ out)
{
    extern __shared__ float sm[];
    float* Qs = sm + QS_OFF;
    float* Ks = sm + KS_OFF;
    float* Ps = sm + PS_OFF;
    float* Vs = sm + VS_OFF;

    const int b  = blockIdx.y;
    const int t0 = blockIdx.x * TT;
    const int tid = threadIdx.x;
    const int tr = tid >> 4;   // 0..15
    const int cc = tid & 15;   // 0..15

    // Load Q tile [32][64]
#pragma unroll
    for (int k = 0; k < 2; k++) {
        int f = tid + 256 * k;
        int c = f >> 4, t4 = f & 15;
        const float4 q = *(const float4*)&g_Q[((size_t)b * CQK_ + c) * T_ + t0 + t4 * 4];
        *(float4*)&Qs[c * 68 + t4 * 4] = q;
    }

    float o[4][16];
    float m_i[4], l_i[4];
#pragma unroll
    for (int i = 0; i < 4; i++) {
        m_i[i] = -1e30f; l_i[i] = 0.f;
#pragma unroll
        for (int j = 0; j < 16; j++) o[i][j] = 0.f;
    }

    for (int s0 = 0; s0 < T_; s0 += TS) {
        // ---- load K tile 32x32 ----
        {
            int c = tid >> 3, s4 = tid & 7;
            const float4 kv = *(const float4*)&g_K[((size_t)b * CQK_ + c) * T_ + s0 + s4 * 4];
            *(float4*)&Ks[c * 36 + s4 * 4] = kv;
        }
        // ---- load V tile 256x32, transpose to Vs[s][c] (stride 257) ----
#pragma unroll
        for (int k = 0; k < 8; k++) {
            int f = tid + 256 * k;
            int c = f >> 3, s4 = f & 7;
            const float4 vv = *(const float4*)&g_V[((size_t)b * C_ + c) * T_ + s0 + s4 * 4];
            Vs[(s4 * 4 + 0) * 257 + c] = vv.x;
            Vs[(s4 * 4 + 1) * 257 + c] = vv.y;
            Vs[(s4 * 4 + 2) * 257 + c] = vv.z;
            Vs[(s4 * 4 + 3) * 257 + c] = vv.w;
        }
        __syncthreads();

        // ---- S = Q^T K : rows tr*4+i, cols cc and cc+16 ----
        float sv[4][2];
#pragma unroll
        for (int i = 0; i < 4; i++) { sv[i][0] = 0.f; sv[i][1] = 0.f; }
#pragma unroll 8
        for (int c = 0; c < 32; c++) {
            const float ks0 = Ks[c * 36 + cc];
            const float ks1 = Ks[c * 36 + cc + 16];
#pragma unroll
            for (int i = 0; i < 4; i++) {
                const float q = Qs[c * 68 + tr * 4 + i];
                sv[i][0] += q * ks0;
                sv[i][1] += q * ks1;
            }
        }

        // ---- online softmax (rows co-owned by 16 lanes) ----
#pragma unroll
        for (int i = 0; i < 4; i++) {
            float mx = fmaxf(sv[i][0], sv[i][1]);
#pragma unroll
            for (int off = 8; off >= 1; off >>= 1)
                mx = fmaxf(mx, __shfl_xor_sync(0xffffffffu, mx, off));
            const float mnew = fmaxf(m_i[i], mx);
            const float fac  = __expf(m_i[i] - mnew);
            const float p0 = __expf(sv[i][0] - mnew);
            const float p1 = __expf(sv[i][1] - mnew);
            float rs = p0 + p1;
#pragma unroll
            for (int off = 8; off >= 1; off >>= 1)
                rs += __shfl_xor_sync(0xffffffffu, rs, off);
            l_i[i] = l_i[i] * fac + rs;
            m_i[i] = mnew;
#pragma unroll
            for (int j = 0; j < 16; j++) o[i][j] *= fac;
            Ps[(tr * 4 + i) * 33 + cc]      = p0;
            Ps[(tr * 4 + i) * 33 + cc + 16] = p1;
        }
        __syncthreads();

        // ---- O += P @ V^T ----
#pragma unroll 4
        for (int s = 0; s < TS; s++) {
            float p_[4];
#pragma unroll
            for (int i = 0; i < 4; i++) p_[i] = Ps[(tr * 4 + i) * 33 + s];
            const float* vrow = &Vs[s * 257 + cc];
#pragma unroll
            for (int j = 0; j < 16; j++) {
                const float v = vrow[16 * j];
#pragma unroll
                for (int i = 0; i < 4; i++) o[i][j] += p_[i] * v;
            }
        }
        __syncthreads();
    }

    // ---- epilogue: out = O/l + x ----
#pragma unroll
    for (int i = 0; i < 4; i++) {
        const float inv = 1.0f / l_i[i];
        const int t = t0 + tr * 4 + i;
#pragma unroll
        for (int j = 0; j < 16; j++) {
            const int c = cc + 16 * j;
            const size_t idx = ((size_t)b * C_ + c) * T_ + t;
            out[idx] = o[i][j] * inv + x[idx];
        }
    }
}

// ---------------------------------------------------------------------------
extern "C" void kernel_launch(void* const* d_in, const int* in_sizes, int n_in,
                              void* d_out, int out_size)
{
    const float* x  = (const float*)d_in[0];
    const float* Wq = (const float*)d_in[1];
    const float* bq = (const float*)d_in[2];
    const float* Wk = (const float*)d_in[3];
    const float* bk = (const float*)d_in[4];
    const float* Wv = (const float*)d_in[5];
    const float* bv = (const float*)d_in[6];
    float* out = (float*)d_out;

    float *qp, *kp, *vp;
    cudaGetSymbolAddress((void**)&qp, g_Q);
    cudaGetSymbolAddress((void**)&kp, g_K);
    cudaGetSymbolAddress((void**)&vp, g_V);

    const size_t smem = SMEM_FLOATS * sizeof(float);  // ~54.7 KB
    cudaFuncSetAttribute(attn_kernel, cudaFuncAttributeMaxDynamicSharedMemorySize, (int)smem);

    proj_kernel<<<dim3(T_ / 128, 1, B_), 256>>>(x, Wq, bq, qp, CQK_);
    proj_kernel<<<dim3(T_ / 128, 1, B_), 256>>>(x, Wk, bk, kp, CQK_);
    proj_kernel<<<dim3(T_ / 128, 8, B_), 256>>>(x, Wv, bv, vp, C_);
    attn_kernel<<<dim3(T_ / TT, B_), 256, smem>>>(x, out);
}